// round 8
// baseline (speedup 1.0000x reference)
#include <cuda_runtime.h>
#include <cuda_bf16.h>

// ---- constants from the reference ----
#define ELE_FACTOR 332.0637f
#define EWALD_F    1.12837917f
#define EWALD_P    0.3275911f
#define EA0        0.254829592f
#define EA1       -0.284496736f
#define EA2        1.421413741f
#define EA3       -1.453152027f
#define EA4        1.061405429f
#define COUL_BETA  18.7f
#define COUL_R0    2.2f
#define G_EWALD    0.3f
#define R6_SHIFT   8303.765625f   // 4.5^6
#define INV_CUT6   1.0e-6f        // 1/10^6

#define MAX_ATOMS 200000

// packed per-atom data (charge, sqrt(c6), r0, pad). 3.2 MB, L2-resident.
__device__ float4 g_atoms[MAX_ATOMS];

__global__ void pack_atoms_kernel(const float* __restrict__ q,
                                  const float* __restrict__ c6,
                                  const float* __restrict__ r0,
                                  int n) {
    int i = blockIdx.x * blockDim.x + threadIdx.x;
    if (i < n) {
        g_atoms[i] = make_float4(q[i], sqrtf(c6[i]), r0[i], 0.0f);
    }
}

// Per-edge physics from pre-reduced pair scalars.
// qq = qi*qj, c6ij = sqrt(c6i)*sqrt(c6j), r0s = r0i + r0j.
__device__ __forceinline__ void edge_compute(
    float dx, float dy, float dz, float qq, float c6ij, float r0s,
    float& ecoul, float& edisp, float& fc, float& fd)
{
    float r2     = dx * dx + dy * dy + dz * dz;
    float rinv   = rsqrtf(r2);
    float rij    = r2 * rinv;
    float inv_r2 = rinv * rinv;

    // ---------------- Coulomb ----------------
    float prefactor = ELE_FACTOR * qq * rinv;

    float x  = (COUL_BETA / COUL_R0) * (rij - COUL_R0);
    float ex = __expf(-fabsf(x));                     // in (0, 1]
    float inv1pex = __fdividef(1.0f, 1.0f + ex);
    float damp = (x >= 0.0f) ? inv1pex : (ex * inv1pex);   // stable sigmoid
    // softplus(x)/beta, stable
    float sp = (fmaxf(x, 0.0f) + __logf(1.0f + ex)) * (1.0f / COUL_BETA);
    float s  = rij * (1.0f / COUL_R0) * __fdividef(1.0f, 1.0f + sp);

    // Ewald short-range erfc correction
    float grij  = G_EWALD * rij;
    float expm2 = __expf(-grij * grij);
    float t     = __fdividef(1.0f, 1.0f + EWALD_P * grij);
    float erfc  = t * (EA0 + t * (EA1 + t * (EA2 + t * (EA3 + t * EA4)))) * expm2;

    ecoul = prefactor * (s + (erfc - 1.0f));
    float fcoul = prefactor * (damp * s * s + erfc + EWALD_F * grij * expm2 - 1.0f);
    fc = fcoul * inv_r2;

    // ---------------- Dispersion (D3-CSO) ----------------
    float r6     = r2 * r2 * r2 + R6_SHIFT;
    float inv_r6 = __fdividef(1.0f, r6);
    float e      = __expf(rij - 1.25f * r0s);          // rij - 2.5*r0ij
    float inv1pe = __fdividef(1.0f, 1.0f + e);
    float cso    = 0.85f + 0.82f * inv1pe;

    edisp = -c6ij * inv_r6 * cso + c6ij * INV_CUT6;
    float r5    = r2 * r2 * rij;
    float fdisp = -6.0f * c6ij * r5 * inv_r6 * inv_r6 * cso
                  - c6ij * inv_r6 * (0.82f * e * inv1pe * inv1pe);
    fd = fdisp * rinv;
}

// 4 edges per thread; all streaming traffic 128-bit; pipelined gathers;
// progressive output stores to keep register pressure under the 5-block cap.
__global__ void __launch_bounds__(256, 5)
bamboo_edge_kernel4(const int4*   __restrict__ row4,
                    const int4*   __restrict__ col4,
                    const float4* __restrict__ dij4,
                    float*        __restrict__ out,
                    int E, int nquads) {
    int t = blockIdx.x * blockDim.x + threadIdx.x;
    if (t >= nquads) return;

    int4 r4 = row4[t];
    int4 c4 = col4[t];

    // gathers for edges 0,1 first (4 in flight)
    float4 A0 = __ldg(&g_atoms[r4.x]);
    float4 B0 = __ldg(&g_atoms[c4.x]);
    float4 A1 = __ldg(&g_atoms[r4.y]);
    float4 B1 = __ldg(&g_atoms[c4.y]);

    float4 d0 = dij4[3 * t + 0];
    float4 d1 = dij4[3 * t + 1];
    float4 d2 = dij4[3 * t + 2];

    // reduce pair 0,1 to scalars; release gather regs
    float qq0 = A0.x * B0.x, c60 = A0.y * B0.y, rs0 = A0.z + B0.z;
    float qq1 = A1.x * B1.x, c61 = A1.y * B1.y, rs1 = A1.z + B1.z;

    // issue gathers for edges 2,3 (overlap with compute of 0,1)
    float4 A2 = __ldg(&g_atoms[r4.z]);
    float4 B2 = __ldg(&g_atoms[c4.z]);
    float4 A3 = __ldg(&g_atoms[r4.w]);
    float4 B3 = __ldg(&g_atoms[c4.w]);

    float ec0, ec1, ec2, ec3, ed0, ed1, ed2, ed3;
    float fc, fd;

    float4* cfp = reinterpret_cast<float4*>(out + (size_t)E) + 3 * t;
    float4* dfp = reinterpret_cast<float4*>(out + (size_t)5 * E) + 3 * t;

    // edge 0: dij = (d0.x, d0.y, d0.z)
    edge_compute(d0.x, d0.y, d0.z, qq0, c60, rs0, ec0, ed0, fc, fd);
    float cfx0 = d0.x * fc, cfy0 = d0.y * fc, cfz0 = d0.z * fc;
    float dfx0 = d0.x * fd, dfy0 = d0.y * fd, dfz0 = d0.z * fd;

    // edge 1: dij = (d0.w, d1.x, d1.y)
    edge_compute(d0.w, d1.x, d1.y, qq1, c61, rs1, ec1, ed1, fc, fd);
    // cf quad 0 complete: [cf0.x cf0.y cf0.z cf1.x]
    cfp[0] = make_float4(cfx0, cfy0, cfz0, d0.w * fc);
    dfp[0] = make_float4(dfx0, dfy0, dfz0, d0.w * fd);
    float cfy1 = d1.x * fc, cfz1 = d1.y * fc;   // carry cf1.y, cf1.z
    float dfy1 = d1.x * fd, dfz1 = d1.y * fd;

    // reduce pair 2,3
    float qq2 = A2.x * B2.x, c62 = A2.y * B2.y, rs2 = A2.z + B2.z;
    float qq3 = A3.x * B3.x, c63 = A3.y * B3.y, rs3 = A3.z + B3.z;

    // edge 2: dij = (d1.z, d1.w, d2.x)
    edge_compute(d1.z, d1.w, d2.x, qq2, c62, rs2, ec2, ed2, fc, fd);
    // cf quad 1 complete: [cf1.y cf1.z cf2.x cf2.y]
    cfp[1] = make_float4(cfy1, cfz1, d1.z * fc, d1.w * fc);
    dfp[1] = make_float4(dfy1, dfz1, d1.z * fd, d1.w * fd);
    float cfz2 = d2.x * fc;
    float dfz2 = d2.x * fd;

    // edge 3: dij = (d2.y, d2.z, d2.w)
    edge_compute(d2.y, d2.z, d2.w, qq3, c63, rs3, ec3, ed3, fc, fd);
    // cf quad 2 complete: [cf2.z cf3.x cf3.y cf3.z]
    cfp[2] = make_float4(cfz2, d2.y * fc, d2.z * fc, d2.w * fc);
    dfp[2] = make_float4(dfz2, d2.y * fd, d2.z * fd, d2.w * fd);

    // energies
    reinterpret_cast<float4*>(out)[t] = make_float4(ec0, ec1, ec2, ec3);
    reinterpret_cast<float4*>(out + (size_t)4 * E)[t] = make_float4(ed0, ed1, ed2, ed3);
}

// scalar tail for E not divisible by 4
__global__ void bamboo_edge_tail(const int*   __restrict__ row,
                                 const int*   __restrict__ col,
                                 const float* __restrict__ dij,
                                 float*       __restrict__ out,
                                 int E, int start) {
    int i = start + blockIdx.x * blockDim.x + threadIdx.x;
    if (i >= E) return;
    float dx = dij[3 * i + 0], dy = dij[3 * i + 1], dz = dij[3 * i + 2];
    float4 A = __ldg(&g_atoms[row[i]]);
    float4 B = __ldg(&g_atoms[col[i]]);
    float ecoul, edisp, fc, fd;
    edge_compute(dx, dy, dz, A.x * B.x, A.y * B.y, A.z + B.z,
                 ecoul, edisp, fc, fd);
    out[i] = ecoul;
    float* cf = out + (size_t)E + 3 * i;
    cf[0] = dx * fc; cf[1] = dy * fc; cf[2] = dz * fc;
    out[(size_t)4 * E + i] = edisp;
    float* df = out + (size_t)5 * E + 3 * i;
    df[0] = dx * fd; df[1] = dy * fd; df[2] = dz * fd;
}

extern "C" void kernel_launch(void* const* d_in, const int* in_sizes, int n_in,
                              void* d_out, int out_size) {
    const int*   row    = (const int*)d_in[0];
    const int*   col    = (const int*)d_in[1];
    const float* dij    = (const float*)d_in[2];
    const float* charge = (const float*)d_in[3];
    const float* c6     = (const float*)d_in[4];
    const float* r0     = (const float*)d_in[5];
    float* out = (float*)d_out;

    int E = in_sizes[0];
    int N = in_sizes[3];

    const int tpb = 256;
    pack_atoms_kernel<<<(N + tpb - 1) / tpb, tpb>>>(charge, c6, r0, N);

    int nquads = E >> 2;
    if (nquads > 0) {
        bamboo_edge_kernel4<<<(nquads + tpb - 1) / tpb, tpb>>>(
            (const int4*)row, (const int4*)col, (const float4*)dij, out, E, nquads);
    }
    int rem = E - (nquads << 2);
    if (rem > 0) {
        bamboo_edge_tail<<<1, tpb>>>(row, col, dij, out, E, nquads << 2);
    }
}

// round 10
// speedup vs baseline: 1.1546x; 1.1546x over previous
#include <cuda_runtime.h>
#include <cuda_bf16.h>

// ---- constants from the reference ----
#define ELE_FACTOR 332.0637f
#define EWALD_F    1.12837917f
#define EWALD_P    0.3275911f
#define EA0        0.254829592f
#define EA1       -0.284496736f
#define EA2        1.421413741f
#define EA3       -1.453152027f
#define EA4        1.061405429f
#define COUL_BETA  18.7f
#define COUL_R0    2.2f
#define G_EWALD    0.3f
#define R6_SHIFT   8303.765625f   // 4.5^6
#define INV_CUT6   1.0e-6f        // 1/10^6

#define MAX_ATOMS 200000

// packed per-atom data (charge, sqrt(c6), r0, pad). 3.2 MB, L2-resident.
__device__ float4 g_atoms[MAX_ATOMS];

__global__ void pack_atoms_kernel(const float* __restrict__ q,
                                  const float* __restrict__ c6,
                                  const float* __restrict__ r0,
                                  int n) {
    int i = blockIdx.x * blockDim.x + threadIdx.x;
    if (i < n) {
        g_atoms[i] = make_float4(q[i], sqrtf(c6[i]), r0[i], 0.0f);
    }
}

// Per-edge physics from pre-reduced pair scalars.
// qq = qi*qj, c6ij = sqrt(c6i)*sqrt(c6j), r0s = r0i + r0j.
__device__ __forceinline__ void edge_compute(
    float dx, float dy, float dz, float qq, float c6ij, float r0s,
    float& ecoul, float& edisp, float& fc, float& fd)
{
    float r2     = dx * dx + dy * dy + dz * dz;
    float rinv   = rsqrtf(r2);
    float rij    = r2 * rinv;
    float inv_r2 = rinv * rinv;

    // ---------------- Coulomb ----------------
    float prefactor = ELE_FACTOR * qq * rinv;

    float x  = (COUL_BETA / COUL_R0) * (rij - COUL_R0);
    float ex = __expf(-fabsf(x));                     // in (0, 1]
    float inv1pex = __fdividef(1.0f, 1.0f + ex);
    float damp = (x >= 0.0f) ? inv1pex : (ex * inv1pex);   // stable sigmoid
    // softplus(x)/beta, stable
    float sp = (fmaxf(x, 0.0f) + __logf(1.0f + ex)) * (1.0f / COUL_BETA);
    float s  = rij * (1.0f / COUL_R0) * __fdividef(1.0f, 1.0f + sp);

    // Ewald short-range erfc correction
    float grij  = G_EWALD * rij;
    float expm2 = __expf(-grij * grij);
    float t     = __fdividef(1.0f, 1.0f + EWALD_P * grij);
    float erfc  = t * (EA0 + t * (EA1 + t * (EA2 + t * (EA3 + t * EA4)))) * expm2;

    ecoul = prefactor * (s + (erfc - 1.0f));
    float fcoul = prefactor * (damp * s * s + erfc + EWALD_F * grij * expm2 - 1.0f);
    fc = fcoul * inv_r2;

    // ---------------- Dispersion (D3-CSO) ----------------
    float r6     = r2 * r2 * r2 + R6_SHIFT;
    float inv_r6 = __fdividef(1.0f, r6);
    float e      = __expf(rij - 1.25f * r0s);          // rij - 2.5*r0ij
    float inv1pe = __fdividef(1.0f, 1.0f + e);
    float cso    = 0.85f + 0.82f * inv1pe;

    edisp = -c6ij * inv_r6 * cso + c6ij * INV_CUT6;
    float r5    = r2 * r2 * rij;
    float fdisp = -6.0f * c6ij * r5 * inv_r6 * inv_r6 * cso
                  - c6ij * inv_r6 * (0.82f * e * inv1pe * inv1pe);
    fd = fdisp * rinv;
}

// 2 edges per thread. Streaming via float2/int2 (stays at the line-count
// wavefront floor), 4 gathers issued up front for MLP, no occupancy cap.
__global__ void __launch_bounds__(256)
bamboo_edge_kernel2(const int2*   __restrict__ row2,
                    const int2*   __restrict__ col2,
                    const float2* __restrict__ dij2,
                    float*        __restrict__ out,
                    int E, int npairs) {
    int t = blockIdx.x * blockDim.x + threadIdx.x;
    if (t >= npairs) return;

    int2 r2i = row2[t];
    int2 c2i = col2[t];

    // all 4 gathers in flight before any compute
    float4 A0 = __ldg(&g_atoms[r2i.x]);
    float4 B0 = __ldg(&g_atoms[c2i.x]);
    float4 A1 = __ldg(&g_atoms[r2i.y]);
    float4 B1 = __ldg(&g_atoms[c2i.y]);

    // dij for edges 2t, 2t+1: floats [6t, 6t+6) as three float2s
    float2 da = dij2[3 * t + 0];   // e0.x, e0.y
    float2 db = dij2[3 * t + 1];   // e0.z, e1.x
    float2 dc = dij2[3 * t + 2];   // e1.y, e1.z

    // reduce pairs to scalars (gather regs die here)
    float qq0 = A0.x * B0.x, c60 = A0.y * B0.y, rs0 = A0.z + B0.z;
    float qq1 = A1.x * B1.x, c61 = A1.y * B1.y, rs1 = A1.z + B1.z;

    float ec0, ed0, ec1, ed1, fc, fd;

    // edge 0
    edge_compute(da.x, da.y, db.x, qq0, c60, rs0, ec0, ed0, fc, fd);
    float cf0x = da.x * fc, cf0y = da.y * fc, cf0z = db.x * fc;
    float df0x = da.x * fd, df0y = da.y * fd, df0z = db.x * fd;

    // edge 1
    edge_compute(db.y, dc.x, dc.y, qq1, c61, rs1, ec1, ed1, fc, fd);

    // ---- outputs: layout [ecoul E | coul_fij 3E | edisp E | disp_fij 3E] ----
    reinterpret_cast<float2*>(out)[t] = make_float2(ec0, ec1);

    float2* cfp = reinterpret_cast<float2*>(out + (size_t)E) + 3 * t;
    cfp[0] = make_float2(cf0x, cf0y);
    cfp[1] = make_float2(cf0z, db.y * fc);
    cfp[2] = make_float2(dc.x * fc, dc.y * fc);

    reinterpret_cast<float2*>(out + (size_t)4 * E)[t] = make_float2(ed0, ed1);

    float2* dfp = reinterpret_cast<float2*>(out + (size_t)5 * E) + 3 * t;
    dfp[0] = make_float2(df0x, df0y);
    dfp[1] = make_float2(df0z, db.y * fd);
    dfp[2] = make_float2(dc.x * fd, dc.y * fd);
}

// scalar tail for odd E
__global__ void bamboo_edge_tail(const int*   __restrict__ row,
                                 const int*   __restrict__ col,
                                 const float* __restrict__ dij,
                                 float*       __restrict__ out,
                                 int E, int start) {
    int i = start + blockIdx.x * blockDim.x + threadIdx.x;
    if (i >= E) return;
    float dx = dij[3 * i + 0], dy = dij[3 * i + 1], dz = dij[3 * i + 2];
    float4 A = __ldg(&g_atoms[row[i]]);
    float4 B = __ldg(&g_atoms[col[i]]);
    float ecoul, edisp, fc, fd;
    edge_compute(dx, dy, dz, A.x * B.x, A.y * B.y, A.z + B.z,
                 ecoul, edisp, fc, fd);
    out[i] = ecoul;
    float* cf = out + (size_t)E + 3 * i;
    cf[0] = dx * fc; cf[1] = dy * fc; cf[2] = dz * fc;
    out[(size_t)4 * E + i] = edisp;
    float* df = out + (size_t)5 * E + 3 * i;
    df[0] = dx * fd; df[1] = dy * fd; df[2] = dz * fd;
}

extern "C" void kernel_launch(void* const* d_in, const int* in_sizes, int n_in,
                              void* d_out, int out_size) {
    const int*   row    = (const int*)d_in[0];
    const int*   col    = (const int*)d_in[1];
    const float* dij    = (const float*)d_in[2];
    const float* charge = (const float*)d_in[3];
    const float* c6     = (const float*)d_in[4];
    const float* r0     = (const float*)d_in[5];
    float* out = (float*)d_out;

    int E = in_sizes[0];
    int N = in_sizes[3];

    const int tpb = 256;
    pack_atoms_kernel<<<(N + tpb - 1) / tpb, tpb>>>(charge, c6, r0, N);

    int npairs = E >> 1;
    if (npairs > 0) {
        bamboo_edge_kernel2<<<(npairs + tpb - 1) / tpb, tpb>>>(
            (const int2*)row, (const int2*)col, (const float2*)dij, out, E, npairs);
    }
    if (E & 1) {
        bamboo_edge_tail<<<1, tpb>>>(row, col, dij, out, E, npairs << 1);
    }
}

// round 11
// speedup vs baseline: 1.3188x; 1.1422x over previous
#include <cuda_runtime.h>
#include <cuda_bf16.h>

// ---- constants from the reference ----
#define ELE_FACTOR 332.0637f
#define EWALD_F    1.12837917f
#define EWALD_P    0.3275911f
#define EA0        0.254829592f
#define EA1       -0.284496736f
#define EA2        1.421413741f
#define EA3       -1.453152027f
#define EA4        1.061405429f
#define COUL_BETA  18.7f
#define COUL_R0    2.2f
#define G_EWALD    0.3f
#define R6_SHIFT   8303.765625f   // 4.5^6
#define INV_CUT6   1.0e-6f        // 1/10^6

#define MAX_ATOMS 200000
#define FULLMASK  0xffffffffu

// packed per-atom data (charge, sqrt(c6), r0, pad). 3.2 MB, L2-resident.
__device__ float4 g_atoms[MAX_ATOMS];

__global__ void pack_atoms_kernel(const float* __restrict__ q,
                                  const float* __restrict__ c6,
                                  const float* __restrict__ r0,
                                  int n) {
    int i = blockIdx.x * blockDim.x + threadIdx.x;
    if (i < n) {
        g_atoms[i] = make_float4(q[i], sqrtf(c6[i]), r0[i], 0.0f);
    }
}

// Per-edge physics from pre-reduced pair scalars.
// qq = qi*qj, c6ij = sqrt(c6i)*sqrt(c6j), r0s = r0i + r0j.
__device__ __forceinline__ void edge_compute(
    float dx, float dy, float dz, float qq, float c6ij, float r0s,
    float& ecoul, float& edisp, float& fc, float& fd)
{
    float r2     = dx * dx + dy * dy + dz * dz;
    float rinv   = rsqrtf(r2);
    float rij    = r2 * rinv;
    float inv_r2 = rinv * rinv;

    // ---------------- Coulomb ----------------
    float prefactor = ELE_FACTOR * qq * rinv;

    float x  = (COUL_BETA / COUL_R0) * (rij - COUL_R0);
    float ex = __expf(-fabsf(x));                     // in (0, 1]
    float inv1pex = __fdividef(1.0f, 1.0f + ex);
    float damp = (x >= 0.0f) ? inv1pex : (ex * inv1pex);   // stable sigmoid
    // softplus(x)/beta, stable
    float sp = (fmaxf(x, 0.0f) + __logf(1.0f + ex)) * (1.0f / COUL_BETA);
    float s  = rij * (1.0f / COUL_R0) * __fdividef(1.0f, 1.0f + sp);

    // Ewald short-range erfc correction
    float grij  = G_EWALD * rij;
    float expm2 = __expf(-grij * grij);
    float t     = __fdividef(1.0f, 1.0f + EWALD_P * grij);
    float erfc  = t * (EA0 + t * (EA1 + t * (EA2 + t * (EA3 + t * EA4)))) * expm2;

    ecoul = prefactor * (s + (erfc - 1.0f));
    float fcoul = prefactor * (damp * s * s + erfc + EWALD_F * grij * expm2 - 1.0f);
    fc = fcoul * inv_r2;

    // ---------------- Dispersion (D3-CSO) ----------------
    float r6     = r2 * r2 * r2 + R6_SHIFT;
    float inv_r6 = __fdividef(1.0f, r6);
    float e      = __expf(rij - 1.25f * r0s);          // rij - 2.5*r0ij
    float inv1pe = __fdividef(1.0f, 1.0f + e);
    float cso    = 0.85f + 0.82f * inv1pe;

    edisp = -c6ij * inv_r6 * cso + c6ij * INV_CUT6;
    float r5    = r2 * r2 * rij;
    float fdisp = -6.0f * c6ij * r5 * inv_r6 * inv_r6 * cso
                  - c6ij * inv_r6 * (0.82f * e * inv1pe * inv1pe);
    fd = fdisp * rinv;
}

// 1 edge/thread scalar compute; dij loads and cf/df stores are done at the
// 128B-line wavefront floor via warp-cooperative float4 accesses + shuffles.
// Requires E % 4 == 0 for float4 alignment of the cf/df output regions.
__global__ void __launch_bounds__(256)
bamboo_edge_shfl(const int*    __restrict__ row,
                 const int*    __restrict__ col,
                 const float4* __restrict__ dij4,
                 float*        __restrict__ out,
                 int E, int nwarps) {
    int tid  = blockIdx.x * blockDim.x + threadIdx.x;
    int w    = tid >> 5;
    int lane = tid & 31;
    if (w >= nwarps) return;

    int i = (w << 5) + lane;            // my edge (warp is always full)

    // gathers first (in flight during all the shuffle work)
    int ri = row[i];
    int ci = col[i];
    float4 A = __ldg(&g_atoms[ri]);
    float4 B = __ldg(&g_atoms[ci]);

    // cooperative dij load: lanes 0..23 load 24 consecutive float4s
    // (the warp's 96 dij floats = 32 edges). 384B = 3 lines = 3 wavefronts.
    float4 D4 = make_float4(0.f, 0.f, 0.f, 0.f);
    if (lane < 24) D4 = dij4[w * 24 + lane];

    // distribute: lane i needs pool floats 3i, 3i+1, 3i+2.
    // pool float f lives in lane f>>2, component f&3.
    int f0 = 3 * lane;
    int a  = f0 >> 2;
    int o  = f0 & 3;
    float va0 = __shfl_sync(FULLMASK, D4.x, a);
    float va1 = __shfl_sync(FULLMASK, D4.y, a);
    float va2 = __shfl_sync(FULLMASK, D4.z, a);
    float va3 = __shfl_sync(FULLMASK, D4.w, a);
    float vb0 = __shfl_sync(FULLMASK, D4.x, a + 1);
    float vb1 = __shfl_sync(FULLMASK, D4.y, a + 1);

    bool o1 = (o & 1), o2 = (o & 2);
    // dx = va[o]
    float t01 = o1 ? va1 : va0, t23 = o1 ? va3 : va2;
    float dx  = o2 ? t23 : t01;
    // dy = (o<3) ? va[o+1] : vb0
    float u12 = o1 ? va2 : va1;      // o=0 -> va1, o=1 -> va2
    float u3x = o1 ? vb0 : va3;      // o=2 -> va3, o=3 -> vb0
    float dy  = o2 ? u3x : u12;
    // dz = (o<2) ? va[o+2] : vb[o-2]
    float z01 = o1 ? va3 : va2;
    float z23 = o1 ? vb1 : vb0;
    float dz  = o2 ? z23 : z01;

    float qq = A.x * B.x, c6ij = A.y * B.y, r0s = A.z + B.z;
    float ec, ed, fc, fd;
    edge_compute(dx, dy, dz, qq, c6ij, r0s, ec, ed, fc, fd);

    // energies: coalesced scalar stores (already at the line floor)
    out[i] = ec;
    out[(size_t)4 * E + i] = ed;

    // store transpose: lane j<24 writes output float4 = pool floats [4j, 4j+4)
    // of cf (= dij * fc). Lane j already HOLDS those dij floats in D4; it only
    // needs fc/fd of the 1-2 source edges, fetched by shuffle.
    int g0 = lane << 2;
    int e0 = g0 / 3;                 // first source edge (lane within warp)
    int p  = g0 - 3 * e0;            // 0,1,2
    float fca = __shfl_sync(FULLMASK, fc, e0);
    float fcb = __shfl_sync(FULLMASK, fc, e0 + 1);
    float fda = __shfl_sync(FULLMASK, fd, e0);
    float fdb = __shfl_sync(FULLMASK, fd, e0 + 1);

    // component k source edge: e0 + {0, p==2, p>=1, 1}[k]
    float s1c = (p == 2) ? fcb : fca;
    float s2c = (p == 0) ? fca : fcb;
    float s1d = (p == 2) ? fdb : fda;
    float s2d = (p == 0) ? fda : fdb;

    if (lane < 24) {
        int q4 = (E >> 2);           // float4 count of one E-block (E%4==0)
        float4* o4 = reinterpret_cast<float4*>(out);
        o4[(size_t)q4 + (size_t)w * 24 + lane] =
            make_float4(D4.x * fca, D4.y * s1c, D4.z * s2c, D4.w * fcb);
        o4[(size_t)q4 * 5 + (size_t)w * 24 + lane] =
            make_float4(D4.x * fda, D4.y * s1d, D4.z * s2d, D4.w * fdb);
    }
}

// scalar fallback/tail: handles edges [start, E)
__global__ void bamboo_edge_tail(const int*   __restrict__ row,
                                 const int*   __restrict__ col,
                                 const float* __restrict__ dij,
                                 float*       __restrict__ out,
                                 int E, int start) {
    int i = start + blockIdx.x * blockDim.x + threadIdx.x;
    if (i >= E) return;
    float dx = dij[3 * i + 0], dy = dij[3 * i + 1], dz = dij[3 * i + 2];
    float4 A = __ldg(&g_atoms[row[i]]);
    float4 B = __ldg(&g_atoms[col[i]]);
    float ecoul, edisp, fc, fd;
    edge_compute(dx, dy, dz, A.x * B.x, A.y * B.y, A.z + B.z,
                 ecoul, edisp, fc, fd);
    out[i] = ecoul;
    float* cf = out + (size_t)E + 3 * i;
    cf[0] = dx * fc; cf[1] = dy * fc; cf[2] = dz * fc;
    out[(size_t)4 * E + i] = edisp;
    float* df = out + (size_t)5 * E + 3 * i;
    df[0] = dx * fd; df[1] = dy * fd; df[2] = dz * fd;
}

extern "C" void kernel_launch(void* const* d_in, const int* in_sizes, int n_in,
                              void* d_out, int out_size) {
    const int*   row    = (const int*)d_in[0];
    const int*   col    = (const int*)d_in[1];
    const float* dij    = (const float*)d_in[2];
    const float* charge = (const float*)d_in[3];
    const float* c6     = (const float*)d_in[4];
    const float* r0     = (const float*)d_in[5];
    float* out = (float*)d_out;

    int E = in_sizes[0];
    int N = in_sizes[3];

    const int tpb = 256;
    pack_atoms_kernel<<<(N + tpb - 1) / tpb, tpb>>>(charge, c6, r0, N);

    if ((E & 3) == 0) {
        int nwarps = E >> 5;                     // full warps of 32 edges
        if (nwarps > 0) {
            int threads = nwarps * 32;
            bamboo_edge_shfl<<<(threads + tpb - 1) / tpb, tpb>>>(
                row, col, (const float4*)dij, out, E, nwarps);
        }
        int done = nwarps << 5;
        if (done < E) {
            bamboo_edge_tail<<<1, tpb>>>(row, col, dij, out, E, done);
        }
    } else {
        // alignment fallback: plain scalar over everything
        bamboo_edge_tail<<<(E + tpb - 1) / tpb, tpb>>>(row, col, dij, out, E, 0);
    }
}

// round 12
// speedup vs baseline: 1.3571x; 1.0290x over previous
#include <cuda_runtime.h>
#include <cuda_bf16.h>

// ---- constants from the reference ----
#define ELE_FACTOR 332.0637f
#define EWALD_F    1.12837917f
#define EWALD_P    0.3275911f
#define EA0        0.254829592f
#define EA1       -0.284496736f
#define EA2        1.421413741f
#define EA3       -1.453152027f
#define EA4        1.061405429f
#define COUL_BETA  18.7f
#define COUL_R0    2.2f
#define G_EWALD    0.3f
#define R6_SHIFT   8303.765625f   // 4.5^6
#define INV_CUT6   1.0e-6f        // 1/10^6

#define MAX_ATOMS 200000
#define FULLMASK  0xffffffffu

// packed per-atom data (charge, sqrt(c6), r0, pad). 3.2 MB, L2-resident.
__device__ float4 g_atoms[MAX_ATOMS];

__global__ void pack_atoms_kernel(const float* __restrict__ q,
                                  const float* __restrict__ c6,
                                  const float* __restrict__ r0,
                                  int n) {
    int i = blockIdx.x * blockDim.x + threadIdx.x;
    if (i < n) {
        g_atoms[i] = make_float4(q[i], sqrtf(c6[i]), r0[i], 0.0f);
    }
}

// Per-edge physics from pre-reduced pair scalars.
// qq = qi*qj, c6ij = sqrt(c6i)*sqrt(c6j), r0s = r0i + r0j.
__device__ __forceinline__ void edge_compute(
    float dx, float dy, float dz, float qq, float c6ij, float r0s,
    float& ecoul, float& edisp, float& fc, float& fd)
{
    float r2     = dx * dx + dy * dy + dz * dz;
    float rinv   = rsqrtf(r2);
    float rij    = r2 * rinv;
    float inv_r2 = rinv * rinv;

    // ---------------- Coulomb ----------------
    float prefactor = ELE_FACTOR * qq * rinv;

    float x  = (COUL_BETA / COUL_R0) * (rij - COUL_R0);
    float ex = __expf(-fabsf(x));                     // in (0, 1]
    float inv1pex = __fdividef(1.0f, 1.0f + ex);
    float damp = (x >= 0.0f) ? inv1pex : (ex * inv1pex);   // stable sigmoid
    // softplus(x)/beta, stable
    float sp = (fmaxf(x, 0.0f) + __logf(1.0f + ex)) * (1.0f / COUL_BETA);
    float s  = rij * (1.0f / COUL_R0) * __fdividef(1.0f, 1.0f + sp);

    // Ewald short-range erfc correction
    float grij  = G_EWALD * rij;
    float expm2 = __expf(-grij * grij);
    float t     = __fdividef(1.0f, 1.0f + EWALD_P * grij);
    float erfc  = t * (EA0 + t * (EA1 + t * (EA2 + t * (EA3 + t * EA4)))) * expm2;

    ecoul = prefactor * (s + (erfc - 1.0f));
    float fcoul = prefactor * (damp * s * s + erfc + EWALD_F * grij * expm2 - 1.0f);
    fc = fcoul * inv_r2;

    // ---------------- Dispersion (D3-CSO) ----------------
    float r6     = r2 * r2 * r2 + R6_SHIFT;
    float inv_r6 = __fdividef(1.0f, r6);
    float e      = __expf(rij - 1.25f * r0s);          // rij - 2.5*r0ij
    float inv1pe = __fdividef(1.0f, 1.0f + e);
    float cso    = 0.85f + 0.82f * inv1pe;

    edisp = -c6ij * inv_r6 * cso + c6ij * INV_CUT6;
    float r5    = r2 * r2 * rij;
    float fdisp = -6.0f * c6ij * r5 * inv_r6 * inv_r6 * cso
                  - c6ij * inv_r6 * (0.82f * e * inv1pe * inv1pe);
    fd = fdisp * rinv;
}

// 1 edge/thread scalar compute; dij loads and cf/df stores are done at the
// 128B-line wavefront floor via warp-cooperative float4 accesses + shuffles.
// Cache ops: gathers bypass L1 (__ldcg: table is L2-resident, L1 fills are
// wasted bandwidth); streaming loads are read-once (__ldcs); all stores are
// write-once streaming (__stcs). Requires E % 4 == 0.
__global__ void __launch_bounds__(256)
bamboo_edge_shfl(const int*    __restrict__ row,
                 const int*    __restrict__ col,
                 const float4* __restrict__ dij4,
                 float*        __restrict__ out,
                 int E, int nwarps) {
    int tid  = blockIdx.x * blockDim.x + threadIdx.x;
    int w    = tid >> 5;
    int lane = tid & 31;
    if (w >= nwarps) return;

    int i = (w << 5) + lane;            // my edge (warp is always full)

    // gathers first (in flight during all the shuffle work)
    int ri = __ldcs(&row[i]);
    int ci = __ldcs(&col[i]);
    float4 A = __ldcg(&g_atoms[ri]);
    float4 B = __ldcg(&g_atoms[ci]);

    // cooperative dij load: lanes 0..23 load 24 consecutive float4s
    // (the warp's 96 dij floats = 32 edges). 384B = 3 lines = 3 wavefronts.
    float4 D4 = make_float4(0.f, 0.f, 0.f, 0.f);
    if (lane < 24) D4 = __ldcs(&dij4[w * 24 + lane]);

    // distribute: lane i needs pool floats 3i, 3i+1, 3i+2.
    // pool float f lives in lane f>>2, component f&3.
    int f0 = 3 * lane;
    int a  = f0 >> 2;
    int o  = f0 & 3;
    float va0 = __shfl_sync(FULLMASK, D4.x, a);
    float va1 = __shfl_sync(FULLMASK, D4.y, a);
    float va2 = __shfl_sync(FULLMASK, D4.z, a);
    float va3 = __shfl_sync(FULLMASK, D4.w, a);
    float vb0 = __shfl_sync(FULLMASK, D4.x, a + 1);
    float vb1 = __shfl_sync(FULLMASK, D4.y, a + 1);

    bool o1 = (o & 1), o2 = (o & 2);
    // dx = va[o]
    float t01 = o1 ? va1 : va0, t23 = o1 ? va3 : va2;
    float dx  = o2 ? t23 : t01;
    // dy = (o<3) ? va[o+1] : vb0
    float u12 = o1 ? va2 : va1;      // o=0 -> va1, o=1 -> va2
    float u3x = o1 ? vb0 : va3;      // o=2 -> va3, o=3 -> vb0
    float dy  = o2 ? u3x : u12;
    // dz = (o<2) ? va[o+2] : vb[o-2]
    float z01 = o1 ? va3 : va2;
    float z23 = o1 ? vb1 : vb0;
    float dz  = o2 ? z23 : z01;

    float qq = A.x * B.x, c6ij = A.y * B.y, r0s = A.z + B.z;
    float ec, ed, fc, fd;
    edge_compute(dx, dy, dz, qq, c6ij, r0s, ec, ed, fc, fd);

    // energies: coalesced scalar stores (already at the line floor)
    __stcs(&out[i], ec);
    __stcs(&out[(size_t)4 * E + i], ed);

    // store transpose: lane j<24 writes output float4 = pool floats [4j, 4j+4)
    // of cf (= dij * fc). Lane j already HOLDS those dij floats in D4; it only
    // needs fc/fd of the 1-2 source edges, fetched by shuffle.
    int g0 = lane << 2;
    int e0 = g0 / 3;                 // first source edge (lane within warp)
    int p  = g0 - 3 * e0;            // 0,1,2
    float fca = __shfl_sync(FULLMASK, fc, e0);
    float fcb = __shfl_sync(FULLMASK, fc, e0 + 1);
    float fda = __shfl_sync(FULLMASK, fd, e0);
    float fdb = __shfl_sync(FULLMASK, fd, e0 + 1);

    // component k source edge: e0 + {0, p==2, p>=1, 1}[k]
    float s1c = (p == 2) ? fcb : fca;
    float s2c = (p == 0) ? fca : fcb;
    float s1d = (p == 2) ? fdb : fda;
    float s2d = (p == 0) ? fda : fdb;

    if (lane < 24) {
        int q4 = (E >> 2);           // float4 count of one E-block (E%4==0)
        float4* o4 = reinterpret_cast<float4*>(out);
        __stcs(&o4[(size_t)q4 + (size_t)w * 24 + lane],
               make_float4(D4.x * fca, D4.y * s1c, D4.z * s2c, D4.w * fcb));
        __stcs(&o4[(size_t)q4 * 5 + (size_t)w * 24 + lane],
               make_float4(D4.x * fda, D4.y * s1d, D4.z * s2d, D4.w * fdb));
    }
}

// scalar fallback/tail: handles edges [start, E)
__global__ void bamboo_edge_tail(const int*   __restrict__ row,
                                 const int*   __restrict__ col,
                                 const float* __restrict__ dij,
                                 float*       __restrict__ out,
                                 int E, int start) {
    int i = start + blockIdx.x * blockDim.x + threadIdx.x;
    if (i >= E) return;
    float dx = dij[3 * i + 0], dy = dij[3 * i + 1], dz = dij[3 * i + 2];
    float4 A = __ldcg(&g_atoms[row[i]]);
    float4 B = __ldcg(&g_atoms[col[i]]);
    float ecoul, edisp, fc, fd;
    edge_compute(dx, dy, dz, A.x * B.x, A.y * B.y, A.z + B.z,
                 ecoul, edisp, fc, fd);
    out[i] = ecoul;
    float* cf = out + (size_t)E + 3 * i;
    cf[0] = dx * fc; cf[1] = dy * fc; cf[2] = dz * fc;
    out[(size_t)4 * E + i] = edisp;
    float* df = out + (size_t)5 * E + 3 * i;
    df[0] = dx * fd; df[1] = dy * fd; df[2] = dz * fd;
}

extern "C" void kernel_launch(void* const* d_in, const int* in_sizes, int n_in,
                              void* d_out, int out_size) {
    const int*   row    = (const int*)d_in[0];
    const int*   col    = (const int*)d_in[1];
    const float* dij    = (const float*)d_in[2];
    const float* charge = (const float*)d_in[3];
    const float* c6     = (const float*)d_in[4];
    const float* r0     = (const float*)d_in[5];
    float* out = (float*)d_out;

    int E = in_sizes[0];
    int N = in_sizes[3];

    const int tpb = 256;
    pack_atoms_kernel<<<(N + tpb - 1) / tpb, tpb>>>(charge, c6, r0, N);

    if ((E & 3) == 0) {
        int nwarps = E >> 5;                     // full warps of 32 edges
        if (nwarps > 0) {
            int threads = nwarps * 32;
            bamboo_edge_shfl<<<(threads + tpb - 1) / tpb, tpb>>>(
                row, col, (const float4*)dij, out, E, nwarps);
        }
        int done = nwarps << 5;
        if (done < E) {
            bamboo_edge_tail<<<1, tpb>>>(row, col, dij, out, E, done);
        }
    } else {
        // alignment fallback: plain scalar over everything
        bamboo_edge_tail<<<(E + tpb - 1) / tpb, tpb>>>(row, col, dij, out, E, 0);
    }
}